// round 8
// baseline (speedup 1.0000x reference)
#include <cuda_runtime.h>
#include <cuda_fp16.h>
#include <cstdint>

#define N_TOK   131072
#define DIM     64
#define NE      512
#define TILE_M  256
#define N_TILES 512
#define NTHR    512
#define NCTA    148
#define TAU     1.3e-4f

#define OUT_Q     0ull
#define OUT_DIFF  8388608ull
#define OUT_IND   8388609ull
#define OUT_EMB   8519681ull
#define OUT_CS    8552449ull
#define OUT_AVG   8552961ull

#define SB_HI   0               // codebook hi: 512 x 128B f16, SW128
#define SB_LO   65536           // codebook lo f16
#define SA      131072          // A tile: 256 x 128B f16
#define SSQ     163840          // ||E||^2 exact [512]
#define SSQO    165888          // ||E||^2 + 0.5 [512]
#define SSF     167936          // ||f||^2 [256]
#define SIND    168960          // argmin [256]
#define SHIST   169984          // [512]
#define SLIST   172032          // flagged tokens [256]
#define SCNT    173056
#define SMEM_TOTAL 173088

#define SWZ(o) ((o) ^ (((o) >> 3) & 0x70))

// scratch: starts zero (static init); finalizer resets to zero each call
__device__ float        g_embed_sum[NE * DIM];
__device__ unsigned int g_hist[NE];
__device__ double       g_diff;
__device__ unsigned int g_done;

static __device__ __forceinline__ uint32_t smem_u32(const void* p) {
    uint32_t a;
    asm("{ .reg .u64 t; cvta.to.shared.u64 t, %1; cvt.u32.u64 %0, t; }" : "=r"(a) : "l"(p));
    return a;
}
static __device__ __forceinline__ uint32_t h2u(__half2 v) {
    uint32_t u; memcpy(&u, &v, 4); return u;
}
static __device__ __forceinline__ float2 u2f2(uint32_t u) {
    __half2 h; memcpy(&h, &u, 4); return __half22float2(h);
}
static __device__ __forceinline__ void mma16816(float* c, const uint32_t* a,
                                                const uint32_t* b) {
    asm volatile(
        "mma.sync.aligned.m16n8k16.row.col.f32.f16.f16.f32 "
        "{%0,%1,%2,%3}, {%4,%5,%6,%7}, {%8,%9}, {%0,%1,%2,%3};"
        : "+f"(c[0]), "+f"(c[1]), "+f"(c[2]), "+f"(c[3])
        : "r"(a[0]), "r"(a[1]), "r"(a[2]), "r"(a[3]), "r"(b[0]), "r"(b[1]));
}
static __device__ __forceinline__ void ldsm4(uint32_t* r, uint32_t addr) {
    asm volatile("ldmatrix.sync.aligned.m8n8.x4.shared.b16 {%0,%1,%2,%3}, [%4];"
                 : "=r"(r[0]), "=r"(r[1]), "=r"(r[2]), "=r"(r[3]) : "r"(addr));
}
static __device__ __forceinline__ void top2(uint32_t& k1, uint32_t& k2, uint32_t k) {
    uint32_t mx = k > k1 ? k : k1;
    k1 = k < k1 ? k : k1;
    k2 = mx < k2 ? mx : k2;
}

__global__ __launch_bounds__(NTHR, 1)
void vq_main(const float* __restrict__ x, const float* __restrict__ embed,
             const float* __restrict__ cs_in, const float* __restrict__ ea_in,
             float* __restrict__ out) {
    extern __shared__ char smc[];
    float*        ssq   = (float*)(smc + SSQ);
    float*        ssqo  = (float*)(smc + SSQO);
    float*        ssf   = (float*)(smc + SSF);
    int*          sind  = (int*)(smc + SIND);
    unsigned int* shist = (unsigned int*)(smc + SHIST);
    int*          slist = (int*)(smc + SLIST);
    int*          scnt  = (int*)(smc + SCNT);
    __shared__ unsigned int s_rank;

    const int tid  = threadIdx.x;
    const int lane = tid & 31;
    const int w    = tid >> 5;
    const uint32_t sbase = smem_u32(smc);

    // ---- prologue ----
    if (tid < NE) shist[tid] = 0u;
    for (int idx = tid; idx < DIM * NE; idx += NTHR) {
        int d = idx >> 9;
        int e = idx & (NE - 1);
        float v = embed[idx];
        __half h = __float2half_rn(v);
        __half l = __float2half_rn(v - __half2float(h));
        uint32_t so = SWZ((uint32_t)(e * 128 + d * 2));
        *(__half*)(smc + SB_HI + so) = h;
        *(__half*)(smc + SB_LO + so) = l;
    }
    if (tid < NE) {
        float s = 0.0f;
#pragma unroll
        for (int d = 0; d < DIM; d++) {
            float v = embed[d * NE + tid];
            s = __fmaf_rn(v, v, s);
        }
        ssq[tid]  = s;
        ssqo[tid] = s + 0.5f;
    }
    __syncthreads();

    const int mat  = lane >> 3;
    const int mrow = lane & 7;
    const int q    = lane >> 2;
    const int cq   = lane & 3;
    const int token = tid >> 1;
    const int half  = tid & 1;

    for (int tile = blockIdx.x; tile < N_TILES; tile += NCTA) {
        // ---- phase 1: f16 convert + ||f||^2 (2 threads/token) ----
        if (tid == 0) *scnt = 0;
        const float4* xr = (const float4*)(x + ((size_t)tile * TILE_M + token) * DIM
                                           + half * 32);
        float s0 = 0.f, s1 = 0.f, s2 = 0.f, s3 = 0.f;
#pragma unroll
        for (int i = 0; i < 8; i++) {
            float4 v = xr[i];
            s0 = __fmaf_rn(v.x, v.x, s0);
            s1 = __fmaf_rn(v.y, v.y, s1);
            s2 = __fmaf_rn(v.z, v.z, s2);
            s3 = __fmaf_rn(v.w, v.w, s3);
            uint32_t pa = h2u(__float22half2_rn(make_float2(v.x, v.y)));
            uint32_t pb = h2u(__float22half2_rn(make_float2(v.z, v.w)));
            uint32_t so = SWZ((uint32_t)(token * 128 + half * 64 + i * 8));
            *(uint2*)(smc + SA + so) = make_uint2(pa, pb);
        }
        float p = (s0 + s1) + (s2 + s3);
        p += __shfl_xor_sync(0xffffffffu, p, 1);
        if (half == 0) ssf[token] = p;
        __syncthreads();

        // ---- phase 2: warp w owns tokens [w*16, w*16+16) ----
        uint32_t AH[4][4];
#pragma unroll
        for (int ks = 0; ks < 4; ks++) {
            int trow = w * 16 + (mat & 1) * 8 + mrow;
            uint32_t off = SWZ((uint32_t)(trow * 128 + ks * 32 + (mat >> 1) * 16));
            ldsm4(AH[ks], sbase + SA + off);
        }
        uint32_t k1[2] = {~0u, ~0u};
        uint32_t k2[2] = {~0u, ~0u};

#pragma unroll 1
        for (int nb = 0; nb < NE; nb += 16) {
            uint32_t BH[4][4];
#pragma unroll
            for (int ks = 0; ks < 4; ks++) {
                int code = nb + (mat >> 1) * 8 + mrow;
                uint32_t off = SWZ((uint32_t)(code * 128 + ks * 32 + (mat & 1) * 16));
                ldsm4(BH[ks], sbase + SB_HI + off);
            }
            float acc[2][4];
#pragma unroll
            for (int nt = 0; nt < 2; nt++)
#pragma unroll
                for (int r = 0; r < 4; r++) acc[nt][r] = 0.0f;
#pragma unroll
            for (int ks = 0; ks < 4; ks++) {
                mma16816(acc[0], AH[ks], &BH[ks][0]);
                mma16816(acc[1], AH[ks], &BH[ks][2]);
            }
            float2 sqa = *(const float2*)(ssqo + nb + 2 * cq);
            float2 sqb = *(const float2*)(ssqo + nb + 8 + 2 * cq);
            const uint32_t c0 = (uint32_t)(nb + 2 * cq);
#pragma unroll
            for (int hr = 0; hr < 2; hr++) {
                float m0 = __fmaf_rn(-2.f, acc[0][hr * 2 + 0], sqa.x);
                float m1 = __fmaf_rn(-2.f, acc[0][hr * 2 + 1], sqa.y);
                float m2 = __fmaf_rn(-2.f, acc[1][hr * 2 + 0], sqb.x);
                float m3 = __fmaf_rn(-2.f, acc[1][hr * 2 + 1], sqb.y);
                top2(k1[hr], k2[hr], (__float_as_uint(m0) & 0xFFFFFE00u) | c0);
                top2(k1[hr], k2[hr], (__float_as_uint(m1) & 0xFFFFFE00u) | (c0 + 1));
                top2(k1[hr], k2[hr], (__float_as_uint(m2) & 0xFFFFFE00u) | (c0 + 8));
                top2(k1[hr], k2[hr], (__float_as_uint(m3) & 0xFFFFFE00u) | (c0 + 9));
            }
        }
#pragma unroll
        for (int r = 0; r < 2; r++) {
            uint32_t b1 = k1[r], b2 = k2[r];
#pragma unroll
            for (int off = 1; off < 4; off <<= 1) {
                uint32_t o1 = __shfl_xor_sync(0xffffffffu, b1, off);
                uint32_t o2 = __shfl_xor_sync(0xffffffffu, b2, off);
                uint32_t mx = b1 > o1 ? b1 : o1;
                b1 = b1 < o1 ? b1 : o1;
                b2 = b2 < o2 ? b2 : o2;
                b2 = mx < b2 ? mx : b2;
            }
            if (cq == 0) {
                int t = w * 16 + q + r * 8;
                sind[t] = (int)(b1 & 0x1FFu);
                float f1 = __uint_as_float(b1 & 0xFFFFFE00u);
                float f2 = __uint_as_float(b2 & 0xFFFFFE00u);
                if (f2 - f1 < TAU) {
                    int idx = atomicAdd(scnt, 1);
                    slist[idx] = t;
                }
            }
        }
        __syncthreads();

        // ---- phase 2b: exact fp32 rescore of flagged tokens ----
        const int cnt = *scnt;
        for (int i = w; i < cnt; i += 16) {
            const int t = slist[i];
            float xv[DIM];
            const float4* xrr = (const float4*)(x + ((size_t)tile * TILE_M + t) * DIM);
#pragma unroll
            for (int j = 0; j < 16; j++) {
                float4 v = xrr[j];
                xv[4 * j] = v.x; xv[4 * j + 1] = v.y;
                xv[4 * j + 2] = v.z; xv[4 * j + 3] = v.w;
            }
            const float sumf = ssf[t];
            float bb = 3.4028235e38f;
            int   be = 0;
#pragma unroll 1
            for (int g = 0; g < 16; g++) {
                int e = g * 32 + lane;
                float dot = 0.0f;
#pragma unroll
                for (int d = 0; d < DIM; d++)
                    dot = __fmaf_rn(xv[d], embed[d * NE + e], dot);
                float dist = __fmaf_rn(-2.0f, dot, sumf) + ssq[e];
                if (dist < bb) { bb = dist; be = e; }
            }
#pragma unroll
            for (int off = 16; off; off >>= 1) {
                float ob = __shfl_xor_sync(0xffffffffu, bb, off);
                int   oe = __shfl_xor_sync(0xffffffffu, be, off);
                if (ob < bb || (ob == bb && oe < be)) { bb = ob; be = oe; }
            }
            if (lane == 0) sind[t] = be;
        }
        __syncthreads();

        // ---- phase 3: epilogue (2 threads/token) ----
        const int gt  = tile * TILE_M + token;
        const int ind = sind[token];
        if (half == 0) {
            out[OUT_IND + gt] = (float)ind;
            atomicAdd(&shist[ind], 1u);
        }
        const float4* xr2 = (const float4*)(x + (size_t)gt * DIM + half * 32);
        float4* oq = (float4*)(out + OUT_Q + (size_t)gt * DIM + half * 32);
        float*  es = g_embed_sum + ind * DIM + half * 32;
        float dsum = 0.0f;
#pragma unroll
        for (int j = 0; j < 4; j++) {
            uint32_t qoff = SWZ((uint32_t)(ind * 128 + half * 64 + j * 16));
            uint4 hq = *(const uint4*)(smc + SB_HI + qoff);
            uint4 lq = *(const uint4*)(smc + SB_LO + qoff);
            float2 h0 = u2f2(hq.x), l0 = u2f2(lq.x);
            float2 h1 = u2f2(hq.y), l1 = u2f2(lq.y);
            float2 h2 = u2f2(hq.z), l2 = u2f2(lq.z);
            float2 h3 = u2f2(hq.w), l3 = u2f2(lq.w);
            float q0 = h0.x + l0.x, q1 = h0.y + l0.y;
            float q2 = h1.x + l1.x, q3 = h1.y + l1.y;
            float q4 = h2.x + l2.x, q5 = h2.y + l2.y;
            float q6 = h3.x + l3.x, q7 = h3.y + l3.y;
            float4 xa = xr2[2 * j];
            float4 xb = xr2[2 * j + 1];
            float e0 = q0 - xa.x, e1 = q1 - xa.y, e2 = q2 - xa.z, e3 = q3 - xa.w;
            float e4 = q4 - xb.x, e5 = q5 - xb.y, e6 = q6 - xb.z, e7 = q7 - xb.w;
            dsum += e0 * e0 + e1 * e1 + e2 * e2 + e3 * e3
                  + e4 * e4 + e5 * e5 + e6 * e6 + e7 * e7;
            oq[2 * j]     = make_float4(xa.x + e0, xa.y + e1, xa.z + e2, xa.w + e3);
            oq[2 * j + 1] = make_float4(xb.x + e4, xb.y + e5, xb.z + e6, xb.w + e7);
            atomicAdd(&es[8 * j + 0], xa.x);
            atomicAdd(&es[8 * j + 1], xa.y);
            atomicAdd(&es[8 * j + 2], xa.z);
            atomicAdd(&es[8 * j + 3], xa.w);
            atomicAdd(&es[8 * j + 4], xb.x);
            atomicAdd(&es[8 * j + 5], xb.y);
            atomicAdd(&es[8 * j + 6], xb.z);
            atomicAdd(&es[8 * j + 7], xb.w);
        }
#pragma unroll
        for (int o = 16; o; o >>= 1) dsum += __shfl_xor_sync(0xffffffffu, dsum, o);
        if (lane == 0) atomicAdd(&g_diff, (double)dsum);

        __syncthreads();
    }

    // ---- merge per-CTA hist, then last CTA finalizes + resets scratch ----
    if (tid < NE && shist[tid]) atomicAdd(&g_hist[tid], shist[tid]);
    __threadfence();
    if (tid == 0) s_rank = atomicAdd(&g_done, 1u);
    __syncthreads();

    if (s_rank == NCTA - 1) {
        const int e = tid;   // NTHR == NE == 512
        float ncs = cs_in[e] * 0.99f + 0.01f * (float)g_hist[e];
        out[OUT_CS + e] = ncs;

        ssq[e] = ncs;        // reuse smem for the n-reduction
        __syncthreads();
        for (int o = 256; o; o >>= 1) {
            if (e < o) ssq[e] += ssq[e + o];
            __syncthreads();
        }
        const float n   = ssq[0];
        const float csn = (ncs + 1e-5f) / (n + 0.00512f) * n;

#pragma unroll 4
        for (int d = 0; d < DIM; d++) {
            int idx = d * NE + e;
            float avg = ea_in[idx] * 0.99f + 0.01f * g_embed_sum[e * DIM + d];
            out[OUT_AVG + idx] = avg;
            out[OUT_EMB + idx] = avg / csn;
            g_embed_sum[e * DIM + d] = 0.0f;     // reset for next replay
        }
        g_hist[e] = 0u;
        if (e == 0) {
            out[OUT_DIFF] = (float)(g_diff * (1.0 / 8388608.0));
            g_diff = 0.0;
            g_done = 0u;
        }
    }
}

extern "C" void kernel_launch(void* const* d_in, const int* in_sizes, int n_in,
                              void* d_out, int out_size) {
    const float* x     = (const float*)d_in[0];
    const float* embed = (const float*)d_in[1];
    const float* cs    = (const float*)d_in[2];
    const float* ea    = (const float*)d_in[3];
    float* out = (float*)d_out;

    cudaFuncSetAttribute(vq_main, cudaFuncAttributeMaxDynamicSharedMemorySize, SMEM_TOTAL);
    vq_main<<<NCTA, NTHR, SMEM_TOTAL>>>(x, embed, cs, ea, out);
}

// round 9
// speedup vs baseline: 1.1741x; 1.1741x over previous
#include <cuda_runtime.h>
#include <cuda_fp16.h>
#include <cstdint>

#define N_TOK   131072
#define DIM     64
#define NE      512
#define TILE_M  128
#define N_TILES 1024
#define NTHR    256
#define NCTA    296
#define TAU     1.3e-4f

#define OUT_Q     0ull
#define OUT_DIFF  8388608ull
#define OUT_IND   8388609ull
#define OUT_EMB   8519681ull
#define OUT_CS    8552449ull
#define OUT_AVG   8552961ull

// smem layout (byte offsets)
#define SB_HI   0               // codebook hi: 512 x 128B f16, SW128 (64KB)
#define SA      65536           // A tile: 128 x 128B f16 (16KB)
#define SSQ     81920           // ||E||^2 exact [512]
#define SSQO    83968           // ||E||^2 + 0.5 [512]
#define SSF     86016           // ||f||^2 [128]
#define SIND    86528           // argmin [128]
#define SHIST   87040           // [512]
#define SLIST   89088           // flagged tokens [128]
#define SCNT    89600
#define SMEM_TOTAL 89616

#define SWZ(o) ((o) ^ (((o) >> 3) & 0x70))

// scratch: starts zero (static init); finalizer resets after use each launch
__device__ float        g_embed_sum[NE * DIM];
__device__ unsigned int g_hist[NE];
__device__ double       g_diff;
__device__ unsigned int g_done;

static __device__ __forceinline__ uint32_t smem_u32(const void* p) {
    uint32_t a;
    asm("{ .reg .u64 t; cvta.to.shared.u64 t, %1; cvt.u32.u64 %0, t; }" : "=r"(a) : "l"(p));
    return a;
}
static __device__ __forceinline__ uint32_t h2u(__half2 v) {
    uint32_t u; memcpy(&u, &v, 4); return u;
}
static __device__ __forceinline__ void mma16816(float* c, const uint32_t* a,
                                                const uint32_t* b) {
    asm volatile(
        "mma.sync.aligned.m16n8k16.row.col.f32.f16.f16.f32 "
        "{%0,%1,%2,%3}, {%4,%5,%6,%7}, {%8,%9}, {%0,%1,%2,%3};"
        : "+f"(c[0]), "+f"(c[1]), "+f"(c[2]), "+f"(c[3])
        : "r"(a[0]), "r"(a[1]), "r"(a[2]), "r"(a[3]), "r"(b[0]), "r"(b[1]));
}
static __device__ __forceinline__ void ldsm4(uint32_t* r, uint32_t addr) {
    asm volatile("ldmatrix.sync.aligned.m8n8.x4.shared.b16 {%0,%1,%2,%3}, [%4];"
                 : "=r"(r[0]), "=r"(r[1]), "=r"(r[2]), "=r"(r[3]) : "r"(addr));
}
static __device__ __forceinline__ void top2(uint32_t& k1, uint32_t& k2, uint32_t k) {
    uint32_t mx = k > k1 ? k : k1;
    k1 = k < k1 ? k : k1;
    k2 = mx < k2 ? mx : k2;
}

__global__ __launch_bounds__(NTHR, 2)
void vq_main(const float* __restrict__ x, const float* __restrict__ embed,
             const float* __restrict__ cs_in, const float* __restrict__ ea_in,
             float* __restrict__ out) {
    extern __shared__ char smc[];
    float*        ssq   = (float*)(smc + SSQ);
    float*        ssqo  = (float*)(smc + SSQO);
    float*        ssf   = (float*)(smc + SSF);
    int*          sind  = (int*)(smc + SIND);
    unsigned int* shist = (unsigned int*)(smc + SHIST);
    int*          slist = (int*)(smc + SLIST);
    int*          scnt  = (int*)(smc + SCNT);
    __shared__ unsigned int s_rank;

    const int tid  = threadIdx.x;
    const int lane = tid & 31;
    const int w    = tid >> 5;
    const uint32_t sbase = smem_u32(smc);

    // ---- prologue: f16-hi codebook + exact ||E||^2 ----
    for (int e = tid; e < NE; e += NTHR) shist[e] = 0u;
    for (int idx = tid; idx < DIM * NE; idx += NTHR) {
        int d = idx >> 9;
        int e = idx & (NE - 1);
        uint32_t so = SWZ((uint32_t)(e * 128 + d * 2));
        *(__half*)(smc + SB_HI + so) = __float2half_rn(embed[idx]);
    }
    for (int e = tid; e < NE; e += NTHR) {
        float s = 0.0f;
#pragma unroll
        for (int d = 0; d < DIM; d++) {
            float v = embed[d * NE + e];
            s = __fmaf_rn(v, v, s);
        }
        ssq[e]  = s;
        ssqo[e] = s + 0.5f;
    }
    __syncthreads();

    const int mat   = lane >> 3;
    const int mrow  = lane & 7;
    const int q     = lane >> 2;
    const int cq    = lane & 3;
    const int token = tid >> 1;    // phases 1/3: 2 threads per token
    const int half  = tid & 1;

    for (int tile = blockIdx.x; tile < N_TILES; tile += NCTA) {
        // ---- phase 1: f16 convert + ||f||^2 ----
        if (tid == 0) *scnt = 0;
        const float4* xr = (const float4*)(x + ((size_t)tile * TILE_M + token) * DIM
                                           + half * 32);
        float s0 = 0.f, s1 = 0.f, s2 = 0.f, s3 = 0.f;
#pragma unroll
        for (int i = 0; i < 8; i++) {
            float4 v = xr[i];
            s0 = __fmaf_rn(v.x, v.x, s0);
            s1 = __fmaf_rn(v.y, v.y, s1);
            s2 = __fmaf_rn(v.z, v.z, s2);
            s3 = __fmaf_rn(v.w, v.w, s3);
            uint32_t pa = h2u(__float22half2_rn(make_float2(v.x, v.y)));
            uint32_t pb = h2u(__float22half2_rn(make_float2(v.z, v.w)));
            uint32_t so = SWZ((uint32_t)(token * 128 + half * 64 + i * 8));
            *(uint2*)(smc + SA + so) = make_uint2(pa, pb);
        }
        float p = (s0 + s1) + (s2 + s3);
        p += __shfl_xor_sync(0xffffffffu, p, 1);
        if (half == 0) ssf[token] = p;
        __syncthreads();

        // ---- phase 2: warp w owns tokens [w*16, w*16+16); 32 codes / iter ----
        uint32_t AH[4][4];
#pragma unroll
        for (int ks = 0; ks < 4; ks++) {
            int trow = w * 16 + (mat & 1) * 8 + mrow;
            uint32_t off = SWZ((uint32_t)(trow * 128 + ks * 32 + (mat >> 1) * 16));
            ldsm4(AH[ks], sbase + SA + off);
        }
        uint32_t k1a[2] = {~0u, ~0u}, k2a[2] = {~0u, ~0u};
        uint32_t k1b[2] = {~0u, ~0u}, k2b[2] = {~0u, ~0u};

#pragma unroll 1
        for (int nb = 0; nb < NE; nb += 32) {
            uint32_t B0[4][4], B1[4][4];
#pragma unroll
            for (int ks = 0; ks < 4; ks++) {
                int code0 = nb + (mat >> 1) * 8 + mrow;
                uint32_t o0 = SWZ((uint32_t)(code0 * 128 + ks * 32 + (mat & 1) * 16));
                ldsm4(B0[ks], sbase + SB_HI + o0);
                uint32_t o1 = SWZ((uint32_t)((code0 + 16) * 128 + ks * 32 + (mat & 1) * 16));
                ldsm4(B1[ks], sbase + SB_HI + o1);
            }
            float acc[4][4];
#pragma unroll
            for (int ng = 0; ng < 4; ng++)
#pragma unroll
                for (int r = 0; r < 4; r++) acc[ng][r] = 0.0f;
#pragma unroll
            for (int ks = 0; ks < 4; ks++) {
                mma16816(acc[0], AH[ks], &B0[ks][0]);
                mma16816(acc[1], AH[ks], &B0[ks][2]);
                mma16816(acc[2], AH[ks], &B1[ks][0]);
                mma16816(acc[3], AH[ks], &B1[ks][2]);
            }
            float2 sq0 = *(const float2*)(ssqo + nb      + 2 * cq);
            float2 sq1 = *(const float2*)(ssqo + nb + 8  + 2 * cq);
            float2 sq2 = *(const float2*)(ssqo + nb + 16 + 2 * cq);
            float2 sq3 = *(const float2*)(ssqo + nb + 24 + 2 * cq);
            const uint32_t c0 = (uint32_t)(nb + 2 * cq);
#pragma unroll
            for (int hr = 0; hr < 2; hr++) {
                float m0 = __fmaf_rn(-2.f, acc[0][hr * 2 + 0], sq0.x);
                float m1 = __fmaf_rn(-2.f, acc[0][hr * 2 + 1], sq0.y);
                float m2 = __fmaf_rn(-2.f, acc[1][hr * 2 + 0], sq1.x);
                float m3 = __fmaf_rn(-2.f, acc[1][hr * 2 + 1], sq1.y);
                float m4 = __fmaf_rn(-2.f, acc[2][hr * 2 + 0], sq2.x);
                float m5 = __fmaf_rn(-2.f, acc[2][hr * 2 + 1], sq2.y);
                float m6 = __fmaf_rn(-2.f, acc[3][hr * 2 + 0], sq3.x);
                float m7 = __fmaf_rn(-2.f, acc[3][hr * 2 + 1], sq3.y);
                // two independent chains per row
                top2(k1a[hr], k2a[hr], (__float_as_uint(m0) & 0xFFFFFE00u) | c0);
                top2(k1b[hr], k2b[hr], (__float_as_uint(m2) & 0xFFFFFE00u) | (c0 + 8));
                top2(k1a[hr], k2a[hr], (__float_as_uint(m1) & 0xFFFFFE00u) | (c0 + 1));
                top2(k1b[hr], k2b[hr], (__float_as_uint(m3) & 0xFFFFFE00u) | (c0 + 9));
                top2(k1a[hr], k2a[hr], (__float_as_uint(m4) & 0xFFFFFE00u) | (c0 + 16));
                top2(k1b[hr], k2b[hr], (__float_as_uint(m6) & 0xFFFFFE00u) | (c0 + 24));
                top2(k1a[hr], k2a[hr], (__float_as_uint(m5) & 0xFFFFFE00u) | (c0 + 17));
                top2(k1b[hr], k2b[hr], (__float_as_uint(m7) & 0xFFFFFE00u) | (c0 + 25));
            }
        }
#pragma unroll
        for (int r = 0; r < 2; r++) {
            // merge chains a,b: k1 = min; k2 = min(min(k2a,k2b), max(k1a,k1b))
            uint32_t mx = k1a[r] > k1b[r] ? k1a[r] : k1b[r];
            uint32_t b1 = k1a[r] < k1b[r] ? k1a[r] : k1b[r];
            uint32_t b2 = k2a[r] < k2b[r] ? k2a[r] : k2b[r];
            b2 = mx < b2 ? mx : b2;
#pragma unroll
            for (int off = 1; off < 4; off <<= 1) {
                uint32_t o1 = __shfl_xor_sync(0xffffffffu, b1, off);
                uint32_t o2 = __shfl_xor_sync(0xffffffffu, b2, off);
                uint32_t m2 = b1 > o1 ? b1 : o1;
                b1 = b1 < o1 ? b1 : o1;
                b2 = b2 < o2 ? b2 : o2;
                b2 = m2 < b2 ? m2 : b2;
            }
            if (cq == 0) {
                int t = w * 16 + q + r * 8;
                sind[t] = (int)(b1 & 0x1FFu);
                float f1 = __uint_as_float(b1 & 0xFFFFFE00u);
                float f2 = __uint_as_float(b2 & 0xFFFFFE00u);
                if (f2 - f1 < TAU) {
                    int idx = atomicAdd(scnt, 1);
                    slist[idx] = t;
                }
            }
        }
        __syncthreads();

        // ---- phase 2b: exact fp32 rescore of flagged tokens ----
        const int cnt = *scnt;
        for (int i = w; i < cnt; i += 8) {
            const int t = slist[i];
            float xv[DIM];
            const float4* xrr = (const float4*)(x + ((size_t)tile * TILE_M + t) * DIM);
#pragma unroll
            for (int j = 0; j < 16; j++) {
                float4 v = xrr[j];
                xv[4 * j] = v.x; xv[4 * j + 1] = v.y;
                xv[4 * j + 2] = v.z; xv[4 * j + 3] = v.w;
            }
            const float sumf = ssf[t];
            float bb = 3.4028235e38f;
            int   be = 0;
#pragma unroll 1
            for (int g = 0; g < 16; g++) {
                int e = g * 32 + lane;
                float dot = 0.0f;
#pragma unroll
                for (int d = 0; d < DIM; d++)
                    dot = __fmaf_rn(xv[d], embed[d * NE + e], dot);
                float dist = __fmaf_rn(-2.0f, dot, sumf) + ssq[e];
                if (dist < bb) { bb = dist; be = e; }
            }
#pragma unroll
            for (int off = 16; off; off >>= 1) {
                float ob = __shfl_xor_sync(0xffffffffu, bb, off);
                int   oe = __shfl_xor_sync(0xffffffffu, be, off);
                if (ob < bb || (ob == bb && oe < be)) { bb = ob; be = oe; }
            }
            if (lane == 0) sind[t] = be;
        }
        __syncthreads();

        // ---- phase 3: epilogue (2 threads/token); exact q from global embed ----
        const int gt  = tile * TILE_M + token;
        const int ind = sind[token];
        if (half == 0) {
            out[OUT_IND + gt] = (float)ind;
            atomicAdd(&shist[ind], 1u);
        }
        const float4* xr2 = (const float4*)(x + (size_t)gt * DIM + half * 32);
        float4* oq = (float4*)(out + OUT_Q + (size_t)gt * DIM + half * 32);
        const float* eb = embed + (half * 32) * NE + ind;
        float*  es = g_embed_sum + ind * DIM + half * 32;
        float dsum = 0.0f;
#pragma unroll
        for (int j = 0; j < 4; j++) {
            float q0 = eb[(8 * j + 0) * NE], q1 = eb[(8 * j + 1) * NE];
            float q2 = eb[(8 * j + 2) * NE], q3 = eb[(8 * j + 3) * NE];
            float q4 = eb[(8 * j + 4) * NE], q5 = eb[(8 * j + 5) * NE];
            float q6 = eb[(8 * j + 6) * NE], q7 = eb[(8 * j + 7) * NE];
            float4 xa = xr2[2 * j];
            float4 xb = xr2[2 * j + 1];
            float e0 = q0 - xa.x, e1 = q1 - xa.y, e2 = q2 - xa.z, e3 = q3 - xa.w;
            float e4 = q4 - xb.x, e5 = q5 - xb.y, e6 = q6 - xb.z, e7 = q7 - xb.w;
            dsum += e0 * e0 + e1 * e1 + e2 * e2 + e3 * e3
                  + e4 * e4 + e5 * e5 + e6 * e6 + e7 * e7;
            oq[2 * j]     = make_float4(xa.x + e0, xa.y + e1, xa.z + e2, xa.w + e3);
            oq[2 * j + 1] = make_float4(xb.x + e4, xb.y + e5, xb.z + e6, xb.w + e7);
            atomicAdd(&es[8 * j + 0], xa.x);
            atomicAdd(&es[8 * j + 1], xa.y);
            atomicAdd(&es[8 * j + 2], xa.z);
            atomicAdd(&es[8 * j + 3], xa.w);
            atomicAdd(&es[8 * j + 4], xb.x);
            atomicAdd(&es[8 * j + 5], xb.y);
            atomicAdd(&es[8 * j + 6], xb.z);
            atomicAdd(&es[8 * j + 7], xb.w);
        }
#pragma unroll
        for (int o = 16; o; o >>= 1) dsum += __shfl_xor_sync(0xffffffffu, dsum, o);
        if (lane == 0) atomicAdd(&g_diff, (double)dsum);

        __syncthreads();
    }

    // ---- merge hist; last CTA finalizes + resets scratch ----
    for (int e = tid; e < NE; e += NTHR)
        if (shist[e]) atomicAdd(&g_hist[e], shist[e]);
    __threadfence();
    if (tid == 0) s_rank = atomicAdd(&g_done, 1u);
    __syncthreads();

    if (s_rank == NCTA - 1) {
        for (int e = tid; e < NE; e += NTHR) {
            float ncs = cs_in[e] * 0.99f + 0.01f * (float)g_hist[e];
            out[OUT_CS + e] = ncs;
            ssq[e] = ncs;
        }
        __syncthreads();
        for (int o = 256; o >= 1; o >>= 1) {
            if (tid < o && tid + o < NE) ssq[tid] += ssq[tid + o];
            __syncthreads();
        }
        const float n = ssq[0];
        for (int e = tid; e < NE; e += NTHR) {
            float ncs = out[OUT_CS + e];
            float csn = (ncs + 1e-5f) / (n + 0.00512f) * n;
#pragma unroll 4
            for (int d = 0; d < DIM; d++) {
                int idx = d * NE + e;
                float avg = ea_in[idx] * 0.99f + 0.01f * g_embed_sum[e * DIM + d];
                out[OUT_AVG + idx] = avg;
                out[OUT_EMB + idx] = avg / csn;
                g_embed_sum[e * DIM + d] = 0.0f;   // reset for next replay
            }
            g_hist[e] = 0u;
        }
        if (tid == 0) {
            out[OUT_DIFF] = (float)(g_diff * (1.0 / 8388608.0));
            g_diff = 0.0;
            g_done = 0u;
        }
    }
}

extern "C" void kernel_launch(void* const* d_in, const int* in_sizes, int n_in,
                              void* d_out, int out_size) {
    const float* x     = (const float*)d_in[0];
    const float* embed = (const float*)d_in[1];
    const float* cs    = (const float*)d_in[2];
    const float* ea    = (const float*)d_in[3];
    float* out = (float*)d_out;

    cudaFuncSetAttribute(vq_main, cudaFuncAttributeMaxDynamicSharedMemorySize, SMEM_TOTAL);
    vq_main<<<NCTA, NTHR, SMEM_TOTAL>>>(x, embed, cs, ea, out);
}

// round 10
// speedup vs baseline: 1.5550x; 1.3244x over previous
#include <cuda_runtime.h>
#include <cuda_fp16.h>
#include <cstdint>

#define N_TOK   131072
#define DIM     64
#define NE      512
#define TILE_M  256
#define N_TILES 512
#define NTHR    512
#define NCTA    148
#define TAU     1.3e-4f

#define OUT_Q     0ull
#define OUT_DIFF  8388608ull
#define OUT_IND   8388609ull
#define OUT_EMB   8519681ull
#define OUT_CS    8552449ull
#define OUT_AVG   8552961ull

#define SB_HI   0               // codebook hi: 512 x 128B f16, SW128
#define SB_LO   65536           // codebook lo f16 (exact reconstruction)
#define SA      131072          // A tile: 256 x 128B f16
#define SSQ     163840          // ||E||^2 exact [512]
#define SSQO    165888          // ||E||^2 + 0.5 [512]
#define SSF     167936          // ||f||^2 [256]
#define SIND    168960          // argmin [256]
#define SHIST   169984          // [512]
#define SLIST   172032          // flagged tokens [256]
#define SCNT    173056
#define SMEM_TOTAL 173088

#define SWZ(o) ((o) ^ (((o) >> 3) & 0x70))

// scratch: zero at start (static init); finalizer resets each launch
__device__ float        g_embed_sum[NE * DIM];   // [e][d]
__device__ unsigned int g_hist[NE];
__device__ double       g_diff;
__device__ unsigned int g_done;

static __device__ __forceinline__ uint32_t smem_u32(const void* p) {
    uint32_t a;
    asm("{ .reg .u64 t; cvta.to.shared.u64 t, %1; cvt.u32.u64 %0, t; }" : "=r"(a) : "l"(p));
    return a;
}
static __device__ __forceinline__ uint32_t h2u(__half2 v) {
    uint32_t u; memcpy(&u, &v, 4); return u;
}
static __device__ __forceinline__ float2 u2f2(uint32_t u) {
    __half2 h; memcpy(&h, &u, 4); return __half22float2(h);
}
static __device__ __forceinline__ void mma16816(float* c, const uint32_t* a,
                                                const uint32_t* b) {
    asm volatile(
        "mma.sync.aligned.m16n8k16.row.col.f32.f16.f16.f32 "
        "{%0,%1,%2,%3}, {%4,%5,%6,%7}, {%8,%9}, {%0,%1,%2,%3};"
        : "+f"(c[0]), "+f"(c[1]), "+f"(c[2]), "+f"(c[3])
        : "r"(a[0]), "r"(a[1]), "r"(a[2]), "r"(a[3]), "r"(b[0]), "r"(b[1]));
}
static __device__ __forceinline__ void ldsm4(uint32_t* r, uint32_t addr) {
    asm volatile("ldmatrix.sync.aligned.m8n8.x4.shared.b16 {%0,%1,%2,%3}, [%4];"
                 : "=r"(r[0]), "=r"(r[1]), "=r"(r[2]), "=r"(r[3]) : "r"(addr));
}
static __device__ __forceinline__ void top2(uint32_t& k1, uint32_t& k2, uint32_t k) {
    uint32_t mx = k > k1 ? k : k1;
    k1 = k < k1 ? k : k1;
    k2 = mx < k2 ? mx : k2;
}

__global__ __launch_bounds__(NTHR, 1)
void vq_main(const float* __restrict__ x, const float* __restrict__ embed,
             const float* __restrict__ cs_in, const float* __restrict__ ea_in,
             float* __restrict__ out) {
    extern __shared__ char smc[];
    float*        ssq   = (float*)(smc + SSQ);
    float*        ssqo  = (float*)(smc + SSQO);
    float*        ssf   = (float*)(smc + SSF);
    int*          sind  = (int*)(smc + SIND);
    unsigned int* shist = (unsigned int*)(smc + SHIST);
    int*          slist = (int*)(smc + SLIST);
    int*          scnt  = (int*)(smc + SCNT);
    __shared__ unsigned int s_rank;

    const int tid  = threadIdx.x;
    const int lane = tid & 31;
    const int w    = tid >> 5;
    const uint32_t sbase = smem_u32(smc);

    // ---- prologue: f16 hi/lo codebook + exact ||E||^2 ----
    if (tid < NE) shist[tid] = 0u;
    for (int idx = tid; idx < DIM * NE; idx += NTHR) {
        int d = idx >> 9;
        int e = idx & (NE - 1);
        float v = embed[idx];
        __half h = __float2half_rn(v);
        __half l = __float2half_rn(v - __half2float(h));
        uint32_t so = SWZ((uint32_t)(e * 128 + d * 2));
        *(__half*)(smc + SB_HI + so) = h;
        *(__half*)(smc + SB_LO + so) = l;
    }
    if (tid < NE) {
        float s = 0.0f;
#pragma unroll
        for (int d = 0; d < DIM; d++) {
            float v = embed[d * NE + tid];
            s = __fmaf_rn(v, v, s);
        }
        ssq[tid]  = s;
        ssqo[tid] = s + 0.5f;
    }
    __syncthreads();

    const int mat   = lane >> 3;
    const int mrow  = lane & 7;
    const int q     = lane >> 2;
    const int cq    = lane & 3;
    const int token = tid >> 1;     // phase 1: 2 threads per token
    const int half  = tid & 1;

    float diff_acc = 0.0f;          // per-thread across all tiles

    for (int tile = blockIdx.x; tile < N_TILES; tile += NCTA) {
        // ---- phase 1: f16 convert + ||f||^2 ----
        if (tid == 0) *scnt = 0;
        const float4* xr = (const float4*)(x + ((size_t)tile * TILE_M + token) * DIM
                                           + half * 32);
        float s0 = 0.f, s1 = 0.f, s2 = 0.f, s3 = 0.f;
#pragma unroll
        for (int i = 0; i < 8; i++) {
            float4 v = xr[i];
            s0 = __fmaf_rn(v.x, v.x, s0);
            s1 = __fmaf_rn(v.y, v.y, s1);
            s2 = __fmaf_rn(v.z, v.z, s2);
            s3 = __fmaf_rn(v.w, v.w, s3);
            uint32_t pa = h2u(__float22half2_rn(make_float2(v.x, v.y)));
            uint32_t pb = h2u(__float22half2_rn(make_float2(v.z, v.w)));
            uint32_t so = SWZ((uint32_t)(token * 128 + half * 64 + i * 8));
            *(uint2*)(smc + SA + so) = make_uint2(pa, pb);
        }
        float p = (s0 + s1) + (s2 + s3);
        p += __shfl_xor_sync(0xffffffffu, p, 1);
        if (half == 0) ssf[token] = p;
        __syncthreads();

        // ---- phase 2: warp w owns tokens [w*16, w*16+16) ----
        uint32_t AH[4][4];
#pragma unroll
        for (int ks = 0; ks < 4; ks++) {
            int trow = w * 16 + (mat & 1) * 8 + mrow;
            uint32_t off = SWZ((uint32_t)(trow * 128 + ks * 32 + (mat >> 1) * 16));
            ldsm4(AH[ks], sbase + SA + off);
        }
        uint32_t k1a[2] = {~0u, ~0u}, k2a[2] = {~0u, ~0u};
        uint32_t k1b[2] = {~0u, ~0u}, k2b[2] = {~0u, ~0u};

#pragma unroll 1
        for (int nb = 0; nb < NE; nb += 16) {
            uint32_t BH[4][4];
#pragma unroll
            for (int ks = 0; ks < 4; ks++) {
                int code = nb + (mat >> 1) * 8 + mrow;
                uint32_t off = SWZ((uint32_t)(code * 128 + ks * 32 + (mat & 1) * 16));
                ldsm4(BH[ks], sbase + SB_HI + off);
            }
            float acc[2][4];
#pragma unroll
            for (int nt = 0; nt < 2; nt++)
#pragma unroll
                for (int r = 0; r < 4; r++) acc[nt][r] = 0.0f;
#pragma unroll
            for (int ks = 0; ks < 4; ks++) {
                mma16816(acc[0], AH[ks], &BH[ks][0]);
                mma16816(acc[1], AH[ks], &BH[ks][2]);
            }
            float2 sqa = *(const float2*)(ssqo + nb + 2 * cq);
            float2 sqb = *(const float2*)(ssqo + nb + 8 + 2 * cq);
            const uint32_t c0 = (uint32_t)(nb + 2 * cq);
#pragma unroll
            for (int hr = 0; hr < 2; hr++) {
                float m0 = __fmaf_rn(-2.f, acc[0][hr * 2 + 0], sqa.x);
                float m1 = __fmaf_rn(-2.f, acc[0][hr * 2 + 1], sqa.y);
                float m2 = __fmaf_rn(-2.f, acc[1][hr * 2 + 0], sqb.x);
                float m3 = __fmaf_rn(-2.f, acc[1][hr * 2 + 1], sqb.y);
                // two independent key chains per row
                top2(k1a[hr], k2a[hr], (__float_as_uint(m0) & 0xFFFFFE00u) | c0);
                top2(k1b[hr], k2b[hr], (__float_as_uint(m2) & 0xFFFFFE00u) | (c0 + 8));
                top2(k1a[hr], k2a[hr], (__float_as_uint(m1) & 0xFFFFFE00u) | (c0 + 1));
                top2(k1b[hr], k2b[hr], (__float_as_uint(m3) & 0xFFFFFE00u) | (c0 + 9));
            }
        }
#pragma unroll
        for (int r = 0; r < 2; r++) {
            uint32_t mx = k1a[r] > k1b[r] ? k1a[r] : k1b[r];
            uint32_t b1 = k1a[r] < k1b[r] ? k1a[r] : k1b[r];
            uint32_t b2 = k2a[r] < k2b[r] ? k2a[r] : k2b[r];
            b2 = mx < b2 ? mx : b2;
#pragma unroll
            for (int off = 1; off < 4; off <<= 1) {
                uint32_t o1 = __shfl_xor_sync(0xffffffffu, b1, off);
                uint32_t o2 = __shfl_xor_sync(0xffffffffu, b2, off);
                uint32_t m2 = b1 > o1 ? b1 : o1;
                b1 = b1 < o1 ? b1 : o1;
                b2 = b2 < o2 ? b2 : o2;
                b2 = m2 < b2 ? m2 : b2;
            }
            if (cq == 0) {
                int t = w * 16 + q + r * 8;
                sind[t] = (int)(b1 & 0x1FFu);
                float f1 = __uint_as_float(b1 & 0xFFFFFE00u);
                float f2 = __uint_as_float(b2 & 0xFFFFFE00u);
                if (f2 - f1 < TAU) {
                    int idx = atomicAdd(scnt, 1);
                    slist[idx] = t;
                }
            }
        }
        __syncthreads();

        // ---- phase 2b: exact fp32 rescore (x via broadcast LDG, low reg use) ----
        const int cnt = *scnt;
        for (int i = w; i < cnt; i += 16) {
            const int t = slist[i];
            const float* xp = x + ((size_t)tile * TILE_M + t) * DIM;
            const float sumf = ssf[t];
            float bb = 3.4028235e38f;
            int   be = 0;
#pragma unroll 1
            for (int g = 0; g < 16; g++) {
                int e = g * 32 + lane;
                float dot = 0.0f;
#pragma unroll
                for (int d = 0; d < DIM; d++)
                    dot = __fmaf_rn(xp[d], embed[d * NE + e], dot);
                float dist = __fmaf_rn(-2.0f, dot, sumf) + ssq[e];
                if (dist < bb) { bb = dist; be = e; }
            }
#pragma unroll
            for (int off = 16; off; off >>= 1) {
                float ob = __shfl_xor_sync(0xffffffffu, bb, off);
                int   oe = __shfl_xor_sync(0xffffffffu, be, off);
                if (ob < bb || (ob == bb && oe < be)) { bb = ob; be = oe; }
            }
            if (lane == 0) sind[t] = be;
        }
        __syncthreads();

        // ---- phase 3a: ind output + histogram (coalesced, 256 threads) ----
        if (tid < TILE_M) {
            int ind = sind[tid];
            out[OUT_IND + tile * TILE_M + tid] = (float)ind;
            atomicAdd(&shist[ind], 1u);
        }

        // ---- phase 3b: epilogue, WARP PER TOKEN (lane = dim pair) ----
#pragma unroll 2
        for (int j = 0; j < 16; j++) {
            const int t   = w * 16 + j;
            const int ind = sind[t];                       // broadcast
            const size_t gt = (size_t)tile * TILE_M + t;
            uint32_t so = SWZ((uint32_t)(ind * 128 + lane * 4));  // conflict-free
            float2 h = u2f2(*(const uint32_t*)(smc + SB_HI + so));
            float2 l = u2f2(*(const uint32_t*)(smc + SB_LO + so));
            float q0 = h.x + l.x, q1 = h.y + l.y;          // exact embed value
            float2 xv = *(const float2*)(x + gt * DIM + 2 * lane);  // coalesced
            float e0 = q0 - xv.x, e1 = q1 - xv.y;
            *(float2*)(out + OUT_Q + gt * DIM + 2 * lane) =
                make_float2(xv.x + e0, xv.y + e1);          // coalesced
            diff_acc += e0 * e0 + e1 * e1;
            atomicAdd(&g_embed_sum[ind * DIM + 2 * lane], xv.x);      // packed RED
            atomicAdd(&g_embed_sum[ind * DIM + 2 * lane + 1], xv.y);
        }
        __syncthreads();
    }

    // ---- diff: warp reduce once, one double atomic per warp ----
#pragma unroll
    for (int o = 16; o; o >>= 1) diff_acc += __shfl_xor_sync(0xffffffffu, diff_acc, o);
    if (lane == 0) atomicAdd(&g_diff, (double)diff_acc);

    // ---- merge hist; last CTA finalizes + resets scratch ----
    if (tid < NE && shist[tid]) atomicAdd(&g_hist[tid], shist[tid]);
    __threadfence();
    if (tid == 0) s_rank = atomicAdd(&g_done, 1u);
    __syncthreads();

    if (s_rank == NCTA - 1) {
        const int e = tid;   // NTHR == NE == 512
        float ncs = cs_in[e] * 0.99f + 0.01f * (float)g_hist[e];
        out[OUT_CS + e] = ncs;

        ssq[e] = ncs;
        __syncthreads();
        for (int o = 256; o; o >>= 1) {
            if (e < o) ssq[e] += ssq[e + o];
            __syncthreads();
        }
        const float n   = ssq[0];
        const float csn = (ncs + 1e-5f) / (n + 0.00512f) * n;

#pragma unroll 4
        for (int d = 0; d < DIM; d++) {
            int idx = d * NE + e;
            float avg = ea_in[idx] * 0.99f + 0.01f * g_embed_sum[e * DIM + d];
            out[OUT_AVG + idx] = avg;
            out[OUT_EMB + idx] = avg / csn;
            g_embed_sum[e * DIM + d] = 0.0f;     // reset for next replay
        }
        g_hist[e] = 0u;
        if (e == 0) {
            out[OUT_DIFF] = (float)(g_diff * (1.0 / 8388608.0));
            g_diff = 0.0;
            g_done = 0u;
        }
    }
}

extern "C" void kernel_launch(void* const* d_in, const int* in_sizes, int n_in,
                              void* d_out, int out_size) {
    const float* x     = (const float*)d_in[0];
    const float* embed = (const float*)d_in[1];
    const float* cs    = (const float*)d_in[2];
    const float* ea    = (const float*)d_in[3];
    float* out = (float*)d_out;

    cudaFuncSetAttribute(vq_main, cudaFuncAttributeMaxDynamicSharedMemorySize, SMEM_TOTAL);
    vq_main<<<NCTA, NTHR, SMEM_TOTAL>>>(x, embed, cs, ea, out);
}